// round 4
// baseline (speedup 1.0000x reference)
#include <cuda_runtime.h>

// Half-lattice hop operator, smem-staged K stream:
//   out = DIAG*psi - 0.5 * sum_mu ( K_fwd[mu] @ psi(fwd nbr) + K_bwd[mu] @ psi(bwd nbr) )
// T=Z=Y=16, X/2=8, D=12 complex. mu<3: periodic roll; mu=3: parity-gated X hop.

#define DD 12
#define NV (16*16*16*8)          // 32768 sites
#define DIAGC 4.5f
#define KSTRIDE (NV*DD*DD)       // floats per (mu) slab
#define SLICE (16*DD*DD)         // 2304 floats: K slice for 16 sites, one component
#define SL4 (SLICE/4)            // 576 float4
#define NT 192

__global__ __launch_bounds__(192)
void hop_kernel(const float* __restrict__ psr, const float* __restrict__ psi_,
                const float* __restrict__ Kfr, const float* __restrict__ Kfi,
                const float* __restrict__ Kbr, const float* __restrict__ Kbi,
                float* __restrict__ out)
{
    __shared__ float4 sKr[2][SL4];   // double-buffered K_re slice
    __shared__ float4 sKi[2][SL4];   // double-buffered K_im slice

    const int i   = threadIdx.x;          // 0..11 output row
    const int ty  = threadIdx.y;          // 0..15 site within block
    const int tid = ty * 12 + i;          // 0..191
    const int site = blockIdx.x * 16 + ty;

    // site bits: x [0:3), y [3:7), z [7:11), t [11:15)
    const int x = site & 7;
    const int y = (site >> 3) & 15;
    const int z = (site >> 7) & 15;
    const int t = (site >> 11) & 15;
    const int r = (t + z + y) & 1;

    // neighbor float4-offsets into psi arrays (site*12 floats = site*3 float4)
    const unsigned nTf = ((site & ~(15<<11)) | (((t+1)&15)<<11)) * 3u;
    const unsigned nTb = ((site & ~(15<<11)) | (((t+15)&15)<<11)) * 3u;
    const unsigned nZf = ((site & ~(15<<7))  | (((z+1)&15)<<7)) * 3u;
    const unsigned nZb = ((site & ~(15<<7))  | (((z+15)&15)<<7)) * 3u;
    const unsigned nYf = ((site & ~(15<<3))  | (((y+1)&15)<<3)) * 3u;
    const unsigned nYb = ((site & ~(15<<3))  | (((y+15)&15)<<3)) * 3u;
    const unsigned nXf = (r ? ((site & ~7) | ((x+1)&7)) : site) * 3u;  // fwd iff r==1
    const unsigned nXb = (r ? site : ((site & ~7) | ((x+7)&7))) * 3u;  // bwd iff r==0
    const unsigned nn[8] = {nTf, nTb, nZf, nZb, nYf, nYb, nXf, nXb};

    const unsigned kbase = (unsigned)blockIdx.x * SL4;  // float4 offset of block's K slice
    const float4* pr4 = reinterpret_cast<const float4*>(psr);
    const float4* pi4 = reinterpret_cast<const float4*>(psi_);

    float hr0 = 0.f, hi0 = 0.f, hr1 = 0.f, hi1 = 0.f;

    // ---- stage fetch helper (compile-time s) ----
    float4 fr0, fr1, fr2, fi0, fi1, fi2;
#define FETCH(s) { \
    const float4* gr = reinterpret_cast<const float4*>(((s)&1) ? Kbr : Kfr) \
                       + ((s)>>1) * (KSTRIDE/4) + kbase; \
    const float4* gi = reinterpret_cast<const float4*>(((s)&1) ? Kbi : Kfi) \
                       + ((s)>>1) * (KSTRIDE/4) + kbase; \
    fr0 = __ldg(gr + tid); fr1 = __ldg(gr + tid + NT); fr2 = __ldg(gr + tid + 2*NT); \
    fi0 = __ldg(gi + tid); fi1 = __ldg(gi + tid + NT); fi2 = __ldg(gi + tid + 2*NT); }

#define STORE(buf) { \
    sKr[buf][tid] = fr0; sKr[buf][tid+NT] = fr1; sKr[buf][tid+2*NT] = fr2; \
    sKi[buf][tid] = fi0; sKi[buf][tid+NT] = fi1; sKi[buf][tid+2*NT] = fi2; }

    // prologue: stage 0 into buffer 0
    FETCH(0); STORE(0);

#pragma unroll
    for (int s = 0; s < 8; ++s) {
        if (s < 7) FETCH(s + 1);          // next-stage LDGs in flight during compute
        __syncthreads();                   // buf[s&1] visible to all threads
        {
            const float4* kr = &sKr[s & 1][ty * 36 + i * 3];
            const float4* ki = &sKi[s & 1][ty * 36 + i * 3];
            const float4* vr = pr4 + nn[s];
            const float4* vi = pi4 + nn[s];
#pragma unroll
            for (int c = 0; c < 3; ++c) {
                const float4 krv = kr[c];
                const float4 kiv = ki[c];
                const float4 vrv = __ldg(vr + c);
                const float4 viv = __ldg(vi + c);
                hr0 = fmaf(krv.x, vrv.x, hr0); hr0 = fmaf(-kiv.x, viv.x, hr0);
                hi0 = fmaf(krv.x, viv.x, hi0); hi0 = fmaf( kiv.x, vrv.x, hi0);
                hr1 = fmaf(krv.y, vrv.y, hr1); hr1 = fmaf(-kiv.y, viv.y, hr1);
                hi1 = fmaf(krv.y, viv.y, hi1); hi1 = fmaf( kiv.y, vrv.y, hi1);
                hr0 = fmaf(krv.z, vrv.z, hr0); hr0 = fmaf(-kiv.z, viv.z, hr0);
                hi0 = fmaf(krv.z, viv.z, hi0); hi0 = fmaf( kiv.z, vrv.z, hi0);
                hr1 = fmaf(krv.w, vrv.w, hr1); hr1 = fmaf(-kiv.w, viv.w, hr1);
                hi1 = fmaf(krv.w, viv.w, hi1); hi1 = fmaf( kiv.w, vrv.w, hi1);
            }
        }
        if (s < 7) STORE((s + 1) & 1);
    }
#undef FETCH
#undef STORE

    const unsigned so = (unsigned)site * DD + (unsigned)i;
    const float pre = __ldg(psr + so);
    const float pim = __ldg(psi_ + so);
    out[so]           = DIAGC * pre - 0.5f * (hr0 + hr1);
    out[NV * DD + so] = DIAGC * pim - 0.5f * (hi0 + hi1);
}

extern "C" void kernel_launch(void* const* d_in, const int* in_sizes, int n_in,
                              void* d_out, int out_size)
{
    const float* psr = (const float*)d_in[0];
    const float* psi = (const float*)d_in[1];
    const float* Kfr = (const float*)d_in[2];
    const float* Kfi = (const float*)d_in[3];
    const float* Kbr = (const float*)d_in[4];
    const float* Kbi = (const float*)d_in[5];
    float* out = (float*)d_out;

    dim3 block(12, 16);      // 12 rows x 16 sites = 192 threads
    dim3 grid(NV / 16);      // 2048 blocks
    hop_kernel<<<grid, block>>>(psr, psi, Kfr, Kfi, Kbr, Kbi, out);
}